// round 1
// baseline (speedup 1.0000x reference)
#include <cuda_runtime.h>

// Problem constants
// x: [B=16, C=256, H=32, W=32]  -> viewed as [BC=4096, HW=1024]
// x1[b, p, cij] = x[b, cij, p];  30 layers of per-channel(p) BN+relu6 ODE steps.
// Each channel p (1024 of them) is fully independent: one CTA per channel.

constexpr int BVAL = 16;
constexpr int CVAL = 256;
constexpr int HW   = 1024;
constexpr int BC   = BVAL * CVAL;   // 4096
constexpr int NLAYERS = 30;

// Scratch: transposed input xt[p][bc] and transposed output yt[p][bc]
__device__ float g_xt[(size_t)HW * BC];
__device__ float g_yt[(size_t)HW * BC];

// ---------------------------------------------------------------------------
// Tiled transpose: out[c][r] = in[r][c], in is ROWS x COLS. Dims divide by 32.
// ---------------------------------------------------------------------------
template<int ROWS, int COLS>
__global__ __launch_bounds__(256) void tr_kernel(const float* __restrict__ in,
                                                 float* __restrict__ out) {
    __shared__ float tile[32][33];
    const int bx = blockIdx.x * 32;   // column base (in)
    const int by = blockIdx.y * 32;   // row base (in)
    const int tx = threadIdx.x, ty = threadIdx.y;
#pragma unroll
    for (int j = 0; j < 32; j += 8)
        tile[ty + j][tx] = in[(size_t)(by + ty + j) * COLS + (bx + tx)];
    __syncthreads();
#pragma unroll
    for (int j = 0; j < 32; j += 8)
        out[(size_t)(bx + ty + j) * ROWS + (by + tx)] = tile[tx][ty + j];
}

// ---------------------------------------------------------------------------
// Fused 30-layer ODE kernel. One CTA per channel p. 256 threads.
// Thread t owns elements (b=u, cij=t) for u = 0..15 -> 16 regs each of
// x1, y0, z. Per layer: block-reduce mean/var over the 4096 elements, then
// elementwise update. gamma/beta are per-channel scalars.
// ---------------------------------------------------------------------------
__global__ __launch_bounds__(256) void ode_kernel(
    const float* __restrict__ xt,        // [HW][BC]
    const float* __restrict__ delta_t,   // [NLAYERS]
    const float* __restrict__ matrices,  // [NLAYERS][256]
    const float* __restrict__ gamma,     // [HW]
    const float* __restrict__ beta,      // [HW]
    float* __restrict__ yt)              // [HW][BC]
{
    const int p = blockIdx.x;
    const int t = threadIdx.x;
    const int lane = t & 31;
    const int wid  = t >> 5;

    const float* __restrict__ xp = xt + (size_t)p * BC;

    float x1[16], y0[16], z[16];
#pragma unroll
    for (int u = 0; u < 16; ++u) {
        x1[u] = xp[u * 256 + t];
        y0[u] = x1[u];
    }

    const float gm = gamma[p];
    const float bt = beta[p];

    __shared__ float red_s[8];
    __shared__ float red_q[8];
    __shared__ float bc_ab[2];

    for (int l = 0; l < NLAYERS; ++l) {
        const float mt  = matrices[l * 256 + t];   // m_l[cij = t]
        float dtl = delta_t[l];
        dtl = fminf(fmaxf(dtl, 0.0f), 6.0f);       // relu6(delta_t)
        const float c1 = 1.0f - dtl;

        // pass 1: z = y0 + m*x1, accumulate sum & sumsq
        float s = 0.0f, q = 0.0f;
#pragma unroll
        for (int u = 0; u < 16; ++u) {
            const float zv = fmaf(mt, x1[u], y0[u]);
            z[u] = zv;
            s += zv;
            q = fmaf(zv, zv, q);
        }

        // warp reduce
#pragma unroll
        for (int off = 16; off > 0; off >>= 1) {
            s += __shfl_xor_sync(0xffffffffu, s, off);
            q += __shfl_xor_sync(0xffffffffu, q, off);
        }
        if (lane == 0) { red_s[wid] = s; red_q[wid] = q; }
        __syncthreads();
        if (t == 0) {
            float S = 0.0f, Q = 0.0f;
#pragma unroll
            for (int w = 0; w < 8; ++w) { S += red_s[w]; Q += red_q[w]; }
            const float inv  = 1.0f / 4096.0f;
            const float mean = S * inv;
            const float var  = fmaf(-mean, mean, Q * inv);   // E[z^2]-mu^2 (biased)
            const float rs   = rsqrtf(var + 1e-5f);
            const float a    = gm * rs;
            bc_ab[0] = a;
            bc_ab[1] = fmaf(-mean, a, bt);                    // beta - mean*a
        }
        __syncthreads();
        const float a  = bc_ab[0];
        const float bb = bc_ab[1];

        // pass 2: y0 = (1-dt)*y0 + dt*relu6(a*z + bb)
#pragma unroll
        for (int u = 0; u < 16; ++u) {
            float r = fmaf(z[u], a, bb);
            r = fminf(fmaxf(r, 0.0f), 6.0f);
            y0[u] = fmaf(dtl, r, c1 * y0[u]);
        }
    }

    float* __restrict__ yp = yt + (size_t)p * BC;
#pragma unroll
    for (int u = 0; u < 16; ++u)
        yp[u * 256 + t] = y0[u] + x1[u];
}

// ---------------------------------------------------------------------------
extern "C" void kernel_launch(void* const* d_in, const int* in_sizes, int n_in,
                              void* d_out, int out_size) {
    const float* x    = (const float*)d_in[0];   // [16,256,32,32]
    const float* dt   = (const float*)d_in[1];   // [30,1]
    const float* mat  = (const float*)d_in[2];   // [30,1,1,16,16]
    const float* gm   = (const float*)d_in[3];   // [1024]
    const float* bt   = (const float*)d_in[4];   // [1024]
    float* out = (float*)d_out;                  // [16,256,32,32]

    float *xt, *yt;
    cudaGetSymbolAddress((void**)&xt, g_xt);
    cudaGetSymbolAddress((void**)&yt, g_yt);

    dim3 blk(32, 8);
    // x: [BC=4096 rows, HW=1024 cols] -> xt: [1024, 4096]
    tr_kernel<BC, HW><<<dim3(HW / 32, BC / 32), blk>>>(x, xt);
    // fused 30-layer ODE, one CTA per channel
    ode_kernel<<<HW, 256>>>(xt, dt, mat, gm, bt, yt);
    // yt: [1024 rows, 4096 cols] -> out: [4096, 1024]
    tr_kernel<HW, BC><<<dim3(BC / 32, HW / 32), blk>>>(yt, out);
}